// round 2
// baseline (speedup 1.0000x reference)
#include <cuda_runtime.h>
#include <cstdint>

#define N_DIM   64
#define C_DIM   64
#define HW_DIM  16384
#define BINS    32
#define TOTAL_ELEMS (N_DIM * C_DIM * HW_DIM)   // 67,108,864
#define TOTAL_V4    (TOTAL_ELEMS / 4)          // 16,777,216

// Global scratch for min/max (monotonic-ordered uint encoding of float)
__device__ unsigned int g_minkey;
__device__ unsigned int g_maxkey;

__device__ __forceinline__ unsigned int float_key(float f) {
    unsigned int u = __float_as_uint(f);
    // order-preserving map: negatives -> ~u, non-neg -> u | signbit
    return (u & 0x80000000u) ? ~u : (u | 0x80000000u);
}
__device__ __forceinline__ float key_float(unsigned int k) {
    unsigned int u = (k & 0x80000000u) ? (k & 0x7FFFFFFFu) : ~k;
    return __uint_as_float(u);
}

// Hardware tanh (MUFU.TANH, sm_75+): single-op, ~2^-11 rel accuracy.
__device__ __forceinline__ float htanh(float x) {
    float y;
    asm("tanh.approx.f32 %0, %1;" : "=f"(y) : "f"(x));
    return y;
}

__global__ void init_minmax_kernel() {
    g_minkey = 0xFFFFFFFFu;  // encodes +max float
    g_maxkey = 0x00000000u;  // encodes -max float
}

__global__ void __launch_bounds__(256) minmax_kernel(const float4* __restrict__ x) {
    float vmin =  3.402823466e38f;
    float vmax = -3.402823466e38f;
    int stride = gridDim.x * blockDim.x;
    #pragma unroll 4
    for (int i = blockIdx.x * blockDim.x + threadIdx.x; i < TOTAL_V4; i += stride) {
        float4 v = x[i];
        vmin = fminf(vmin, fminf(fminf(v.x, v.y), fminf(v.z, v.w)));
        vmax = fmaxf(vmax, fmaxf(fmaxf(v.x, v.y), fmaxf(v.z, v.w)));
    }
    // warp reduce
    #pragma unroll
    for (int off = 16; off > 0; off >>= 1) {
        vmin = fminf(vmin, __shfl_xor_sync(0xFFFFFFFFu, vmin, off));
        vmax = fmaxf(vmax, __shfl_xor_sync(0xFFFFFFFFu, vmax, off));
    }
    __shared__ float smin[8], smax[8];
    int wid = threadIdx.x >> 5;
    int lane = threadIdx.x & 31;
    if (lane == 0) { smin[wid] = vmin; smax[wid] = vmax; }
    __syncthreads();
    if (threadIdx.x == 0) {
        float bmin = smin[0], bmax = smax[0];
        #pragma unroll
        for (int w = 1; w < 8; w++) {
            bmin = fminf(bmin, smin[w]);
            bmax = fmaxf(bmax, smax[w]);
        }
        atomicMin(&g_minkey, float_key(bmin));
        atomicMax(&g_maxkey, float_key(bmax));
    }
}

// One block per (n,c) pair: 16384 contiguous floats -> one scalar output.
// z[n,c] = sum_hw tanh(x) * coeff[c, bin(x)]; BINS==32 so the coeff gather
// is a warp shuffle (lane l holds coeff[c][l]).
__global__ void __launch_bounds__(256) hpool_kernel(
    const float* __restrict__ x,
    const float* __restrict__ coeff,
    float* __restrict__ out)
{
    int blk  = blockIdx.x;            // n * C_DIM + c
    int c    = blk & (C_DIM - 1);
    int lane = threadIdx.x & 31;

    float xmin  = key_float(g_minkey);
    float xmax  = key_float(g_maxkey);
    float range = xmax - xmin;
    float scale = (range > 0.f) ? ((float)BINS / range) : 0.f;

    float cw = coeff[c * BINS + lane];

    const float4* xv = (const float4*)(x + (size_t)blk * HW_DIM);
    float acc = 0.f;

    #pragma unroll
    for (int i = 0; i < HW_DIM / (4 * 256); i++) {   // 16 iters
        float4 v = xv[i * 256 + threadIdx.x];
        #pragma unroll
        for (int j = 0; j < 4; j++) {
            float vv = (j == 0) ? v.x : (j == 1) ? v.y : (j == 2) ? v.z : v.w;
            float t = htanh(vv);
            int b = (int)((vv - xmin) * scale);
            b = min(b, BINS - 1);
            float w = __shfl_sync(0xFFFFFFFFu, cw, b);
            acc = fmaf(t, w, acc);
        }
    }

    // block reduce
    #pragma unroll
    for (int off = 16; off > 0; off >>= 1)
        acc += __shfl_xor_sync(0xFFFFFFFFu, acc, off);

    __shared__ float ssum[8];
    int wid = threadIdx.x >> 5;
    if (lane == 0) ssum[wid] = acc;
    __syncthreads();
    if (threadIdx.x == 0) {
        float s = 0.f;
        #pragma unroll
        for (int w = 0; w < 8; w++) s += ssum[w];
        out[blk] = s;
    }
}

extern "C" void kernel_launch(void* const* d_in, const int* in_sizes, int n_in,
                              void* d_out, int out_size) {
    const float* x     = (const float*)d_in[0];
    const float* coeff = (const float*)d_in[1];
    float* out         = (float*)d_out;

    init_minmax_kernel<<<1, 1>>>();
    minmax_kernel<<<4096, 256>>>((const float4*)x);
    hpool_kernel<<<N_DIM * C_DIM, 256>>>(x, coeff, out);
}